// round 5
// baseline (speedup 1.0000x reference)
#include <cuda_runtime.h>
#include <cuda_bf16.h>
#include <cuda_fp16.h>
#include <cstdint>
#include <math.h>

#define DIM      64
#define NREL     16
#define NCOLS    (NREL * DIM)        // 1024
#define MAX_N    120000
#define MAX_E    1600000

// ---- scratch ----
__device__ __align__(256) __half    g_trans[(size_t)MAX_N * NCOLS];  // fp16 now
__device__ __align__(256) float    g_att[MAX_E];
__device__ __align__(256) float    g_ex[MAX_E];
__device__ __align__(256) unsigned g_nmax[MAX_N];
__device__ __align__(256) float    g_denom[MAX_N];

__device__ __forceinline__ unsigned enc_f(float f) {
    unsigned b = __float_as_uint(f);
    return (b & 0x80000000u) ? ~b : (b | 0x80000000u);
}
__device__ __forceinline__ float dec_f(unsigned u) {
    return __uint_as_float((u & 0x80000000u) ? (u & 0x7FFFFFFFu) : ~u);
}

__device__ __forceinline__ uint32_t smem_u32(const void* p) {
    uint32_t a;
    asm("{ .reg .u64 t; cvta.to.shared.u64 t, %1; cvt.u32.u64 %0, t; }"
        : "=r"(a) : "l"(p));
    return a;
}

// ---- warp-mma helpers (family-common PTX; legal on plain sm_103) ----
__device__ __forceinline__ void ldsm_x4(uint32_t addr, uint32_t* r) {
    asm volatile("ldmatrix.sync.aligned.m8n8.x4.shared.b16 {%0,%1,%2,%3}, [%4];"
        : "=r"(r[0]), "=r"(r[1]), "=r"(r[2]), "=r"(r[3]) : "r"(addr));
}
__device__ __forceinline__ void ldsm_x4_t(uint32_t addr, uint32_t* r) {
    asm volatile("ldmatrix.sync.aligned.m8n8.x4.trans.shared.b16 {%0,%1,%2,%3}, [%4];"
        : "=r"(r[0]), "=r"(r[1]), "=r"(r[2]), "=r"(r[3]) : "r"(addr));
}
__device__ __forceinline__ void mma_bf16(float* c, const uint32_t* a,
                                         uint32_t b0, uint32_t b1) {
    asm volatile(
        "mma.sync.aligned.m16n8k16.row.col.f32.bf16.bf16.f32 "
        "{%0,%1,%2,%3}, {%4,%5,%6,%7}, {%8,%9}, {%0,%1,%2,%3};"
        : "+f"(c[0]), "+f"(c[1]), "+f"(c[2]), "+f"(c[3])
        : "r"(a[0]), "r"(a[1]), "r"(a[2]), "r"(a[3]), "r"(b0), "r"(b1));
}

// smem layout (bytes, dynamic): bf16 tiles, 128B rows, XOR-16B swizzle by (row&7)
#define SM_AH   0
#define SM_AL   (SM_AH + 128 * 128)   // 16 KB each
#define SM_BH   (SM_AL + 128 * 128)
#define SM_BL   (SM_BH + 64 * 128)    // 8 KB each
#define SM_TOT  (SM_BL + 64 * 128)    // 49152 B
// output staging reuses SM_AH region after __syncthreads (128 rows x 128 B fp16)
#define SM_OUT  SM_AH

#define SWZ(row, colb) (((uint32_t)(row)) * 128u + (((uint32_t)(colb)) ^ ((((uint32_t)(row)) & 7u) << 4)))

// ---- K1: split-bf16 warp-MMA GEMM + fused init. CTA = 128 rows x 1 relation ----
__global__ __launch_bounds__(256, 4)
void gemm_kernel(const float* __restrict__ emb, const float* __restrict__ W, int M)
{
    extern __shared__ char smem[];
    const uint32_t sb = smem_u32(smem);
    const int tid  = threadIdx.x;
    const int wid  = tid >> 5;
    const int lane = tid & 31;
    const int m0   = blockIdx.x * 128;
    const int rrel = blockIdx.y;
    const float* Wr = W + (size_t)rrel * (DIM * DIM);

    // fused init of per-node accumulators (one relation-slice does it)
    if (rrel == 0 && tid < 128) {
        int gm = m0 + tid;
        if (gm < M) { g_nmax[gm] = 0u; g_denom[gm] = 0.0f; }
    }

    // --- stage A (128x64 fp32 -> bf16 hi/lo) ---
    #pragma unroll
    for (int p = 0; p < 8; p++) {
        int idx = tid + p * 256;          // 0..2047
        int row = idx >> 4;
        int c4  = idx & 15;
        int gm  = m0 + row;
        float4 v = (gm < M) ? ((const float4*)(emb + (size_t)gm * DIM))[c4]
                            : make_float4(0.f, 0.f, 0.f, 0.f);
        __nv_bfloat162 h01 = make_bfloat162(__float2bfloat16(v.x), __float2bfloat16(v.y));
        __nv_bfloat162 h23 = make_bfloat162(__float2bfloat16(v.z), __float2bfloat16(v.w));
        __nv_bfloat162 l01 = make_bfloat162(
            __float2bfloat16(v.x - __bfloat162float(h01.x)),
            __float2bfloat16(v.y - __bfloat162float(h01.y)));
        __nv_bfloat162 l23 = make_bfloat162(
            __float2bfloat16(v.z - __bfloat162float(h23.x)),
            __float2bfloat16(v.w - __bfloat162float(h23.y)));
        uint32_t off = SWZ(row, c4 * 8);
        *(uint2*)(smem + SM_AH + off) = make_uint2(*(uint32_t*)&h01, *(uint32_t*)&h23);
        *(uint2*)(smem + SM_AL + off) = make_uint2(*(uint32_t*)&l01, *(uint32_t*)&l23);
    }
    // --- stage B = W_r ([k=d][n] row-major) as bf16 hi/lo ---
    #pragma unroll
    for (int p = 0; p < 4; p++) {
        int idx = tid + p * 256;          // 0..1023 float4s
        int d  = idx >> 4;
        int c4 = idx & 15;
        float4 v = ((const float4*)Wr)[idx];
        __nv_bfloat162 h01 = make_bfloat162(__float2bfloat16(v.x), __float2bfloat16(v.y));
        __nv_bfloat162 h23 = make_bfloat162(__float2bfloat16(v.z), __float2bfloat16(v.w));
        __nv_bfloat162 l01 = make_bfloat162(
            __float2bfloat16(v.x - __bfloat162float(h01.x)),
            __float2bfloat16(v.y - __bfloat162float(h01.y)));
        __nv_bfloat162 l23 = make_bfloat162(
            __float2bfloat16(v.z - __bfloat162float(h23.x)),
            __float2bfloat16(v.w - __bfloat162float(h23.y)));
        uint32_t off = SWZ(d, c4 * 8);
        *(uint2*)(smem + SM_BH + off) = make_uint2(*(uint32_t*)&h01, *(uint32_t*)&h23);
        *(uint2*)(smem + SM_BL + off) = make_uint2(*(uint32_t*)&l01, *(uint32_t*)&l23);
    }
    __syncthreads();

    const int wr = wid * 16;              // warp's row strip
    float c[8][4];
    #pragma unroll
    for (int t = 0; t < 8; t++)
        #pragma unroll
        for (int j = 0; j < 4; j++) c[t][j] = 0.0f;

    const int a_midx = lane >> 3, a_r = lane & 7;
    const int a_row  = wr + (a_midx & 1) * 8 + a_r;
    const int a_colb0 = (a_midx >> 1) * 16;
    const int b_i    = lane & 7, b_half = lane >> 3;
    const int b_krow0 = (b_half & 1) * 8 + b_i;
    const int b_ncol0 = (b_half >> 1) * 16;

    const uint32_t abase[3] = { sb + SM_AH, sb + SM_AH, sb + SM_AL };
    const uint32_t bbase[3] = { sb + SM_BH, sb + SM_BL, sb + SM_BH };

    #pragma unroll
    for (int ch = 0; ch < 3; ch++) {
        #pragma unroll
        for (int ks = 0; ks < 4; ks++) {
            uint32_t a[4];
            ldsm_x4(abase[ch] + SWZ(a_row, ks * 32 + a_colb0), a);
            #pragma unroll
            for (int np = 0; np < 4; np++) {
                uint32_t b[4];
                int krow = ks * 16 + b_krow0;
                ldsm_x4_t(bbase[ch] + SWZ(krow, np * 32 + b_ncol0), b);
                mma_bf16(c[np * 2 + 0], a, b[0], b[1]);
                mma_bf16(c[np * 2 + 1], a, b[2], b[3]);
            }
        }
    }

    // --- epilogue: stage fp16 tile in smem (reuse A_hi region), then coalesced copy ---
    __syncthreads();   // everyone done reading A/B smem
    {
        int rl0 = wr + (lane >> 2);       // local rows
        int rl1 = rl0 + 8;
        int cb  = (lane & 3) * 4;         // byte offset of half2 within row (fp16)
        #pragma unroll
        for (int t = 0; t < 8; t++) {
            __half2 v0 = __floats2half2_rn(c[t][0], c[t][1]);
            __half2 v1 = __floats2half2_rn(c[t][2], c[t][3]);
            *(__half2*)(smem + SM_OUT + SWZ(rl0, cb + t * 16)) = v0;
            *(__half2*)(smem + SM_OUT + SWZ(rl1, cb + t * 16)) = v1;
        }
    }
    __syncthreads();
    // copy 128 rows x 128 B to g_trans (rows of 8 uint4, coalesced)
    #pragma unroll
    for (int p = 0; p < 4; p++) {
        int idx  = tid + p * 256;         // 0..1023
        int row  = idx >> 3;
        int ch16 = idx & 7;
        int gm   = m0 + row;
        if (gm < M) {
            uint4 v = *(uint4*)(smem + SM_OUT + SWZ(row, ch16 * 16));
            *(uint4*)&g_trans[(size_t)gm * NCOLS + rrel * DIM + ch16 * 8] = v;
        }
    }
}

// ---- K2: per-edge attention logit + segment max (warp per edge, fp16 gathers) ----
__global__ __launch_bounds__(256) void att_kernel(
    const int* __restrict__ src, const int* __restrict__ dst,
    const int* __restrict__ typ, const float* __restrict__ rel, int E)
{
    int gw   = (blockIdx.x * blockDim.x + threadIdx.x) >> 5;
    int lane = threadIdx.x & 31;
    if (gw >= E) return;

    int s = src[gw], d = dst[gw], r = typ[gw];
    const __half2* t  = (const __half2*)(g_trans + (size_t)s * NCOLS + r * DIM);
    const __half2* h  = (const __half2*)(g_trans + (size_t)d * NCOLS + r * DIM);
    const float2*  re = (const float2*)(rel + (size_t)r * DIM);

    float2 tv = __half22float2(t[lane]);
    float2 hv = __half22float2(h[lane]);
    float2 rv = re[lane];
    float p = tv.x * tanhf(hv.x + rv.x) + tv.y * tanhf(hv.y + rv.y);

    #pragma unroll
    for (int o = 16; o > 0; o >>= 1) p += __shfl_xor_sync(0xffffffffu, p, o);

    if (lane == 0) {
        g_att[gw] = p;
        atomicMax(&g_nmax[d], enc_f(p));
    }
}

// ---- K3 ----
__global__ void exp_kernel(const int* __restrict__ dst, int E) {
    int i = blockIdx.x * blockDim.x + threadIdx.x;
    if (i < E) {
        int d  = dst[i];
        float m = dec_f(g_nmax[d]);
        float e = expf(g_att[i] - m);
        g_ex[i] = e;
        atomicAdd(&g_denom[d], e);
    }
}

// ---- K4 ----
__global__ void norm_kernel(const int* __restrict__ dst, float* __restrict__ out, int E) {
    int i = blockIdx.x * blockDim.x + threadIdx.x;
    if (i < E) out[i] = g_ex[i] / g_denom[dst[i]];
}

extern "C" void kernel_launch(void* const* d_in, const int* in_sizes, int n_in,
                              void* d_out, int out_size)
{
    const float* emb = (const float*)d_in[0];
    const float* rel = (const float*)d_in[1];
    const float* W   = (const float*)d_in[2];
    const int*   src = (const int*)d_in[3];
    const int*   dst = (const int*)d_in[4];
    const int*   typ = (const int*)d_in[5];
    float*       out = (float*)d_out;

    int M = in_sizes[0] / DIM;
    int E = in_sizes[3];

    static bool attr_set = false;
    if (!attr_set) {
        cudaFuncSetAttribute(gemm_kernel,
                             cudaFuncAttributeMaxDynamicSharedMemorySize, SM_TOT);
        attr_set = true;
    }

    gemm_kernel<<<dim3((M + 127) / 128, NREL), 256, SM_TOT>>>(emb, W, M);
    att_kernel<<<(E + 7) / 8, 256>>>(src, dst, typ, rel, E);
    exp_kernel<<<(E + 255) / 256, 256>>>(dst, E);
    norm_kernel<<<(E + 255) / 256, 256>>>(dst, out, E);
}

// round 6
// speedup vs baseline: 1.5647x; 1.5647x over previous
#include <cuda_runtime.h>
#include <cuda_fp16.h>
#include <cstdint>
#include <math.h>

#define DIM      64
#define NREL     16
#define NCOLS    (NREL * DIM)        // 1024
#define MAX_N    120000
#define MAX_E    1600000

// ---- scratch ----
__device__ __align__(256) __half    g_trans[(size_t)MAX_N * NCOLS];
__device__ __align__(256) float    g_att[MAX_E];
__device__ __align__(256) float    g_ex[MAX_E];
__device__ __align__(256) unsigned g_nmax[MAX_N];
__device__ __align__(256) float    g_denom[MAX_N];

__device__ __forceinline__ unsigned enc_f(float f) {
    unsigned b = __float_as_uint(f);
    return (b & 0x80000000u) ? ~b : (b | 0x80000000u);
}
__device__ __forceinline__ float dec_f(unsigned u) {
    return __uint_as_float((u & 0x80000000u) ? (u & 0x7FFFFFFFu) : ~u);
}

__device__ __forceinline__ uint32_t smem_u32(const void* p) {
    uint32_t a;
    asm("{ .reg .u64 t; cvta.to.shared.u64 t, %1; cvt.u32.u64 %0, t; }"
        : "=r"(a) : "l"(p));
    return a;
}

// ---- warp-mma helpers (family-common PTX) ----
__device__ __forceinline__ void ldsm_x4(uint32_t addr, uint32_t* r) {
    asm volatile("ldmatrix.sync.aligned.m8n8.x4.shared.b16 {%0,%1,%2,%3}, [%4];"
        : "=r"(r[0]), "=r"(r[1]), "=r"(r[2]), "=r"(r[3]) : "r"(addr));
}
__device__ __forceinline__ void ldsm_x4_t(uint32_t addr, uint32_t* r) {
    asm volatile("ldmatrix.sync.aligned.m8n8.x4.trans.shared.b16 {%0,%1,%2,%3}, [%4];"
        : "=r"(r[0]), "=r"(r[1]), "=r"(r[2]), "=r"(r[3]) : "r"(addr));
}
__device__ __forceinline__ void mma_fp16(float* c, const uint32_t* a,
                                         uint32_t b0, uint32_t b1) {
    asm volatile(
        "mma.sync.aligned.m16n8k16.row.col.f32.f16.f16.f32 "
        "{%0,%1,%2,%3}, {%4,%5,%6,%7}, {%8,%9}, {%0,%1,%2,%3};"
        : "+f"(c[0]), "+f"(c[1]), "+f"(c[2]), "+f"(c[3])
        : "r"(a[0]), "r"(a[1]), "r"(a[2]), "r"(a[3]), "r"(b0), "r"(b1));
}

// smem layout: fp16 tiles, 128B rows, XOR-16B swizzle by (row&7)
#define SM_A    0
#define SM_B    (SM_A + 128 * 128)    // A: 16 KB
#define SM_TOT  (SM_B + 64 * 128)     // B: 8 KB -> 24576 B total
#define SM_OUT  SM_A                  // output staging reuses A after sync

#define SWZ(row, colb) (((uint32_t)(row)) * 128u + (((uint32_t)(colb)) ^ ((((uint32_t)(row)) & 7u) << 4)))

// ---- K1: fp16 warp-MMA GEMM + fused init. CTA = 128 rows x 1 relation ----
__global__ __launch_bounds__(256)
void gemm_kernel(const float* __restrict__ emb, const float* __restrict__ W, int M)
{
    extern __shared__ char smem[];
    const uint32_t sb = smem_u32(smem);
    const int tid  = threadIdx.x;
    const int wid  = tid >> 5;
    const int lane = tid & 31;
    const int m0   = blockIdx.x * 128;
    const int rrel = blockIdx.y;
    const float* Wr = W + (size_t)rrel * (DIM * DIM);

    if (rrel == 0 && tid < 128) {
        int gm = m0 + tid;
        if (gm < M) { g_nmax[gm] = 0u; g_denom[gm] = 0.0f; }
    }

    // --- stage A (128x64 fp32 -> fp16) ---
    #pragma unroll
    for (int p = 0; p < 8; p++) {
        int idx = tid + p * 256;          // 0..2047
        int row = idx >> 4;
        int c4  = idx & 15;
        int gm  = m0 + row;
        float4 v = (gm < M) ? ((const float4*)(emb + (size_t)gm * DIM))[c4]
                            : make_float4(0.f, 0.f, 0.f, 0.f);
        __half2 h01 = __floats2half2_rn(v.x, v.y);
        __half2 h23 = __floats2half2_rn(v.z, v.w);
        *(uint2*)(smem + SM_A + SWZ(row, c4 * 8)) =
            make_uint2(*(uint32_t*)&h01, *(uint32_t*)&h23);
    }
    // --- stage B = W_r ([k=d][n] row-major) as fp16 ---
    #pragma unroll
    for (int p = 0; p < 4; p++) {
        int idx = tid + p * 256;          // 0..1023 float4s
        int d  = idx >> 4;
        int c4 = idx & 15;
        float4 v = ((const float4*)Wr)[idx];
        __half2 h01 = __floats2half2_rn(v.x, v.y);
        __half2 h23 = __floats2half2_rn(v.z, v.w);
        *(uint2*)(smem + SM_B + SWZ(d, c4 * 8)) =
            make_uint2(*(uint32_t*)&h01, *(uint32_t*)&h23);
    }
    __syncthreads();

    const int wr = wid * 16;
    float c[8][4];
    #pragma unroll
    for (int t = 0; t < 8; t++)
        #pragma unroll
        for (int j = 0; j < 4; j++) c[t][j] = 0.0f;

    const int a_midx = lane >> 3, a_r = lane & 7;
    const int a_row  = wr + (a_midx & 1) * 8 + a_r;
    const int a_colb0 = (a_midx >> 1) * 16;
    const int b_i    = lane & 7, b_half = lane >> 3;
    const int b_krow0 = (b_half & 1) * 8 + b_i;
    const int b_ncol0 = (b_half >> 1) * 16;

    #pragma unroll
    for (int ks = 0; ks < 4; ks++) {
        uint32_t a[4];
        ldsm_x4(sb + SM_A + SWZ(a_row, ks * 32 + a_colb0), a);
        #pragma unroll
        for (int np = 0; np < 4; np++) {
            uint32_t b[4];
            int krow = ks * 16 + b_krow0;
            ldsm_x4_t(sb + SM_B + SWZ(krow, np * 32 + b_ncol0), b);
            mma_fp16(c[np * 2 + 0], a, b[0], b[1]);
            mma_fp16(c[np * 2 + 1], a, b[2], b[3]);
        }
    }

    // --- epilogue: stage fp16 tile in smem, then coalesced copy out ---
    __syncthreads();
    {
        int rl0 = wr + (lane >> 2);
        int rl1 = rl0 + 8;
        int cb  = (lane & 3) * 4;
        #pragma unroll
        for (int t = 0; t < 8; t++) {
            __half2 v0 = __floats2half2_rn(c[t][0], c[t][1]);
            __half2 v1 = __floats2half2_rn(c[t][2], c[t][3]);
            *(__half2*)(smem + SM_OUT + SWZ(rl0, cb + t * 16)) = v0;
            *(__half2*)(smem + SM_OUT + SWZ(rl1, cb + t * 16)) = v1;
        }
    }
    __syncthreads();
    #pragma unroll
    for (int p = 0; p < 4; p++) {
        int idx  = tid + p * 256;         // 0..1023
        int row  = idx >> 3;
        int ch16 = idx & 7;
        int gm   = m0 + row;
        if (gm < M) {
            uint4 v = *(uint4*)(smem + SM_OUT + SWZ(row, ch16 * 16));
            *(uint4*)&g_trans[(size_t)gm * NCOLS + rrel * DIM + ch16 * 8] = v;
        }
    }
}

// ---- K2: per-edge attention logit + segment max (warp per edge) ----
__global__ __launch_bounds__(256) void att_kernel(
    const int* __restrict__ src, const int* __restrict__ dst,
    const int* __restrict__ typ, const float* __restrict__ rel, int E)
{
    int gw   = (blockIdx.x * blockDim.x + threadIdx.x) >> 5;
    int lane = threadIdx.x & 31;
    if (gw >= E) return;

    int s = src[gw], d = dst[gw], r = typ[gw];
    const __half2* t  = (const __half2*)(g_trans + (size_t)s * NCOLS + r * DIM);
    const __half2* h  = (const __half2*)(g_trans + (size_t)d * NCOLS + r * DIM);
    const float2*  re = (const float2*)(rel + (size_t)r * DIM);

    float2 tv = __half22float2(t[lane]);
    float2 hv = __half22float2(h[lane]);
    float2 rv = re[lane];
    float p = tv.x * tanhf(hv.x + rv.x) + tv.y * tanhf(hv.y + rv.y);

    #pragma unroll
    for (int o = 16; o > 0; o >>= 1) p += __shfl_xor_sync(0xffffffffu, p, o);

    if (lane == 0) {
        g_att[gw] = p;
        atomicMax(&g_nmax[d], enc_f(p));
    }
}

// ---- K3 ----
__global__ void exp_kernel(const int* __restrict__ dst, int E) {
    int i = blockIdx.x * blockDim.x + threadIdx.x;
    if (i < E) {
        int d  = dst[i];
        float m = dec_f(g_nmax[d]);
        float e = expf(g_att[i] - m);
        g_ex[i] = e;
        atomicAdd(&g_denom[d], e);
    }
}

// ---- K4 ----
__global__ void norm_kernel(const int* __restrict__ dst, float* __restrict__ out, int E) {
    int i = blockIdx.x * blockDim.x + threadIdx.x;
    if (i < E) out[i] = g_ex[i] / g_denom[dst[i]];
}

extern "C" void kernel_launch(void* const* d_in, const int* in_sizes, int n_in,
                              void* d_out, int out_size)
{
    const float* emb = (const float*)d_in[0];
    const float* rel = (const float*)d_in[1];
    const float* W   = (const float*)d_in[2];
    const int*   src = (const int*)d_in[3];
    const int*   dst = (const int*)d_in[4];
    const int*   typ = (const int*)d_in[5];
    float*       out = (float*)d_out;

    int M = in_sizes[0] / DIM;
    int E = in_sizes[3];

    static bool attr_set = false;
    if (!attr_set) {
        cudaFuncSetAttribute(gemm_kernel,
                             cudaFuncAttributeMaxDynamicSharedMemorySize, SM_TOT);
        attr_set = true;
    }

    gemm_kernel<<<dim3((M + 127) / 128, NREL), 256, SM_TOT>>>(emb, W, M);
    att_kernel<<<(E + 7) / 8, 256>>>(src, dst, typ, rel, E);
    exp_kernel<<<(E + 255) / 256, 256>>>(dst, E);
    norm_kernel<<<(E + 255) / 256, 256>>>(dst, out, E);
}